// round 4
// baseline (speedup 1.0000x reference)
#include <cuda_runtime.h>
#include <math.h>

// Problem constants (from reference)
#define B_   2
#define L_   2048
#define D_   1024
#define N_   16
#define R_   64
#define M_   (B_ * L_)        // 4096 rows
#define DBC_ (R_ + 2 * N_)    // 96
#define LC   64               // chunk length
#define NC   (L_ / LC)        // 32 chunks
#define CH   (B_ * D_)        // 2048 channels

// Scratch (no cudaMalloc allowed -> __device__ globals)
__device__ float g_dbc[M_ * DBC_];      // [M, 96]  : delta_low | Bm | Cm
__device__ float g_delta[M_ * D_];      // [M, D]   : softplus(delta_low @ Wup^T + b)
__device__ float g_S[NC * CH];          // per-chunk sum of delta
__device__ float g_hend[NC * CH * N_];  // local chunk-end state (h_in = 0)
__device__ float g_hin[NC * CH * N_];   // corrected chunk-entry state

// ---------------------------------------------------------------------------
// GEMM1: g_dbc[m, j] = sum_k x[m,k] * W_dbc[j,k] + b_dbc[j]
// Tile 32(M) x 96(N) x 64(K), 256 threads (16x16), 2x6 per thread. 128 CTAs.
// ---------------------------------------------------------------------------
__global__ __launch_bounds__(256) void k_gemm_dbc(const float* __restrict__ X,
                                                  const float* __restrict__ W,
                                                  const float* __restrict__ bias) {
    __shared__ float Xs[64][33];  // [k][m]
    __shared__ float Ws[64][97];  // [k][j]
    const int tid = threadIdx.x;
    const int m0  = blockIdx.x * 32;
    const int ty  = tid >> 4;     // 0..15 -> 2 rows each
    const int tx  = tid & 15;     // 0..15 -> 6 cols each

    float acc[2][6];
#pragma unroll
    for (int i = 0; i < 2; i++)
#pragma unroll
        for (int j = 0; j < 6; j++) acc[i][j] = 0.f;

    for (int k0 = 0; k0 < 1024; k0 += 64) {
#pragma unroll
        for (int i = 0; i < 8; i++) {            // 32x64 X tile
            int idx = tid + i * 256;
            int m = idx >> 6, kk = idx & 63;
            Xs[kk][m] = X[(m0 + m) * 1024 + k0 + kk];
        }
#pragma unroll
        for (int i = 0; i < 24; i++) {           // 96x64 W tile
            int idx = tid + i * 256;
            int j = idx >> 6, kk = idx & 63;
            Ws[kk][j] = W[j * 1024 + k0 + kk];
        }
        __syncthreads();
#pragma unroll 8
        for (int kk = 0; kk < 64; kk++) {
            float rm[2], rn[6];
#pragma unroll
            for (int i = 0; i < 2; i++) rm[i] = Xs[kk][ty * 2 + i];
#pragma unroll
            for (int j = 0; j < 6; j++) rn[j] = Ws[kk][tx * 6 + j];
#pragma unroll
            for (int i = 0; i < 2; i++)
#pragma unroll
                for (int j = 0; j < 6; j++) acc[i][j] = fmaf(rm[i], rn[j], acc[i][j]);
        }
        __syncthreads();
    }
#pragma unroll
    for (int i = 0; i < 2; i++)
#pragma unroll
        for (int j = 0; j < 6; j++) {
            int col = tx * 6 + j;
            g_dbc[(m0 + ty * 2 + i) * DBC_ + col] = acc[i][j] + bias[col];
        }
}

// ---------------------------------------------------------------------------
// GEMM2: g_delta[m, d] = softplus( sum_r g_dbc[m, r] * Wup[d, r] + bup[d] )
// Tile 64(M) x 64(D) x 64(K=R), 256 threads, 4x4 per thread. 1024 CTAs.
// ---------------------------------------------------------------------------
__global__ __launch_bounds__(256) void k_gemm_delta(const float* __restrict__ Wup,
                                                    const float* __restrict__ bup) {
    __shared__ float Ls[64][65];  // [r][m]
    __shared__ float Ws[64][65];  // [r][d]
    const int tid = threadIdx.x;
    const int m0 = blockIdx.x * 64;
    const int d0 = blockIdx.y * 64;

#pragma unroll
    for (int i = 0; i < 16; i++) {
        int idx = tid + i * 256;          // 0..4095
        int a = idx >> 6, rr = idx & 63;
        Ls[rr][a] = g_dbc[(m0 + a) * DBC_ + rr];
        Ws[rr][a] = Wup[(d0 + a) * R_ + rr];
    }
    __syncthreads();

    const int ty = tid >> 4, tx = tid & 15;
    float acc[4][4];
#pragma unroll
    for (int i = 0; i < 4; i++)
#pragma unroll
        for (int j = 0; j < 4; j++) acc[i][j] = 0.f;

#pragma unroll 8
    for (int r = 0; r < 64; r++) {
        float rm[4], rn[4];
#pragma unroll
        for (int i = 0; i < 4; i++) rm[i] = Ls[r][ty * 4 + i];
#pragma unroll
        for (int j = 0; j < 4; j++) rn[j] = Ws[r][tx * 4 + j];
#pragma unroll
        for (int i = 0; i < 4; i++)
#pragma unroll
            for (int j = 0; j < 4; j++) acc[i][j] = fmaf(rm[i], rn[j], acc[i][j]);
    }
#pragma unroll
    for (int i = 0; i < 4; i++)
#pragma unroll
        for (int j = 0; j < 4; j++) {
            int dd = d0 + tx * 4 + j;
            float v = acc[i][j] + bup[dd];
            float sp = (v > 20.f) ? v : log1pf(__expf(v));  // softplus
            g_delta[(m0 + ty * 4 + i) * D_ + dd] = sp;
        }
}

// ---------------------------------------------------------------------------
// Helpers
// ---------------------------------------------------------------------------
__device__ __forceinline__ bool load_A(const float* __restrict__ A_log, int d,
                                       float Av[16]) {
    const float4* p = (const float4*)(A_log + d * N_);
    float4 a0 = p[0], a1 = p[1], a2 = p[2], a3 = p[3];
    Av[0] = -__expf(a0.x);  Av[1] = -__expf(a0.y);
    Av[2] = -__expf(a0.z);  Av[3] = -__expf(a0.w);
    Av[4] = -__expf(a1.x);  Av[5] = -__expf(a1.y);
    Av[6] = -__expf(a1.z);  Av[7] = -__expf(a1.w);
    Av[8] = -__expf(a2.x);  Av[9] = -__expf(a2.y);
    Av[10] = -__expf(a2.z); Av[11] = -__expf(a2.w);
    Av[12] = -__expf(a3.x); Av[13] = -__expf(a3.y);
    Av[14] = -__expf(a3.z); Av[15] = -__expf(a3.w);
    bool fast = true;
#pragma unroll
    for (int n = 1; n < 16; n++) {
        float tgt = Av[0] * (float)(n + 1);
        if (fabsf(Av[n] - tgt) > 1e-4f + 1e-5f * fabsf(tgt)) fast = false;
    }
    return fast;
}

__device__ __forceinline__ void load16(const float* __restrict__ p, float v[16]) {
    float4 b0 = *(const float4*)(p);
    float4 b1 = *(const float4*)(p + 4);
    float4 b2 = *(const float4*)(p + 8);
    float4 b3 = *(const float4*)(p + 12);
    v[0] = b0.x;  v[1] = b0.y;  v[2] = b0.z;  v[3] = b0.w;
    v[4] = b1.x;  v[5] = b1.y;  v[6] = b1.z;  v[7] = b1.w;
    v[8] = b2.x;  v[9] = b2.y;  v[10] = b2.z; v[11] = b2.w;
    v[12] = b3.x; v[13] = b3.y; v[14] = b3.z; v[15] = b3.w;
}

#define UF 8   // timestep staging depth in scan kernels

// ---------------------------------------------------------------------------
// Phase A: per (chunk, b, d) local scan with h_in = 0.
// Double-buffered: block t0+UF's delta/x loads issue BEFORE computing block
// t0, so DRAM latency overlaps compute instead of preceding it.
// ---------------------------------------------------------------------------
__global__ __launch_bounds__(256) void k_scanA(const float* __restrict__ x,
                                               const float* __restrict__ A_log) {
    const int g = blockIdx.x * 256 + threadIdx.x;   // 65536 threads
    const int d = g & (D_ - 1);
    const int rest = g >> 10;
    const int b = rest & (B_ - 1);
    const int c = rest >> 1;

    float Av[16];
    const bool fast = load_A(A_log, d, Av);
    const float A0 = Av[0];

    float h[16];
#pragma unroll
    for (int n = 0; n < 16; n++) h[n] = 0.f;
    float S = 0.f;

    const int trow0 = b * L_ + c * LC;
    const float* dptr = g_delta + trow0 * D_ + d;
    const float* xptr = x + trow0 * D_ + d;

    float dts[2][UF], xts[2][UF];
#pragma unroll
    for (int u = 0; u < UF; u++) {       // prologue: fill buffer 0
        dts[0][u] = dptr[u * D_];
        xts[0][u] = xptr[u * D_];
    }

    for (int t0 = 0; t0 < LC; t0 += UF) {
        const int cur = (t0 / UF) & 1;
        const int nxt = cur ^ 1;
        if (t0 + UF < LC) {
#pragma unroll
            for (int u = 0; u < UF; u++) {   // prefetch next block
                dts[nxt][u] = dptr[(t0 + UF + u) * D_];
                xts[nxt][u] = xptr[(t0 + UF + u) * D_];
            }
        }
#pragma unroll
        for (int u = 0; u < UF; u++) {
            float dt = dts[cur][u];
            float xt = xts[cur][u];
            S += dt;
            float dx = dt * xt;
            float bm[16];
            load16(g_dbc + (trow0 + t0 + u) * DBC_ + R_, bm);  // Bm (L2-resident)
            if (fast) {
                float p = __expf(dt * A0);
                float a = p;
#pragma unroll
                for (int n = 0; n < 16; n++) { h[n] = fmaf(a, h[n], dx * bm[n]); a *= p; }
            } else {
#pragma unroll
                for (int n = 0; n < 16; n++)
                    h[n] = fmaf(__expf(dt * Av[n]), h[n], dx * bm[n]);
            }
        }
    }

    const int ch = b * D_ + d;
    float* hp = g_hend + (c * CH + ch) * N_;
    *(float4*)(hp)      = make_float4(h[0], h[1], h[2], h[3]);
    *(float4*)(hp + 4)  = make_float4(h[4], h[5], h[6], h[7]);
    *(float4*)(hp + 8)  = make_float4(h[8], h[9], h[10], h[11]);
    *(float4*)(hp + 12) = make_float4(h[12], h[13], h[14], h[15]);
    g_S[c * CH + ch] = S;
}

// ---------------------------------------------------------------------------
// Phase B: sequential combine across 32 chunks per (channel, n).
// Fully unrolled: all 64 loads in flight at once, then 32 parallel exps,
// then the 32-fma serial chain, then 32 stores. One latency exposure total.
// ---------------------------------------------------------------------------
__global__ __launch_bounds__(256) void k_scanB(const float* __restrict__ A_log) {
    const int g = blockIdx.x * 256 + threadIdx.x;   // 32768 threads
    const int n = g & (N_ - 1);
    const int ch = g >> 4;
    const int d = ch & (D_ - 1);
    const float An = -__expf(A_log[d * N_ + n]);

    float e[NC], hb[NC];
#pragma unroll
    for (int c = 0; c < NC; c++) e[c] = g_S[c * CH + ch];
#pragma unroll
    for (int c = 0; c < NC; c++) hb[c] = g_hend[(c * CH + ch) * N_ + n];
#pragma unroll
    for (int c = 0; c < NC; c++) e[c] = __expf(An * e[c]);

    float h = 0.f;
#pragma unroll
    for (int c = 0; c < NC; c++) {
        g_hin[(c * CH + ch) * N_ + n] = h;
        h = fmaf(e[c], h, hb[c]);
    }
}

// ---------------------------------------------------------------------------
// Phase C: replay each chunk from corrected h_in, emit y_t = sum_n h_n * C_n.
// Same double-buffered pipeline as phase A.
// ---------------------------------------------------------------------------
__global__ __launch_bounds__(256) void k_scanC(const float* __restrict__ x,
                                               const float* __restrict__ A_log,
                                               float* __restrict__ y) {
    const int g = blockIdx.x * 256 + threadIdx.x;   // 65536 threads
    const int d = g & (D_ - 1);
    const int rest = g >> 10;
    const int b = rest & (B_ - 1);
    const int c = rest >> 1;

    float Av[16];
    const bool fast = load_A(A_log, d, Av);
    const float A0 = Av[0];

    const int ch = b * D_ + d;
    float h[16];
    load16(g_hin + (c * CH + ch) * N_, h);

    const int trow0 = b * L_ + c * LC;
    const float* dptr = g_delta + trow0 * D_ + d;
    const float* xptr = x + trow0 * D_ + d;
    float* yptr = y + trow0 * D_ + d;

    float dts[2][UF], xts[2][UF];
#pragma unroll
    for (int u = 0; u < UF; u++) {       // prologue: fill buffer 0
        dts[0][u] = dptr[u * D_];
        xts[0][u] = xptr[u * D_];
    }

    for (int t0 = 0; t0 < LC; t0 += UF) {
        const int cur = (t0 / UF) & 1;
        const int nxt = cur ^ 1;
        if (t0 + UF < LC) {
#pragma unroll
            for (int u = 0; u < UF; u++) {   // prefetch next block
                dts[nxt][u] = dptr[(t0 + UF + u) * D_];
                xts[nxt][u] = xptr[(t0 + UF + u) * D_];
            }
        }
#pragma unroll
        for (int u = 0; u < UF; u++) {
            float dt = dts[cur][u];
            float xt = xts[cur][u];
            float dx = dt * xt;
            const float* row = g_dbc + (trow0 + t0 + u) * DBC_;
            float bm[16], cm[16];
            load16(row + R_, bm);        // Bm
            load16(row + R_ + N_, cm);   // Cm
            float acc = 0.f;
            if (fast) {
                float p = __expf(dt * A0);
                float a = p;
#pragma unroll
                for (int n = 0; n < 16; n++) {
                    h[n] = fmaf(a, h[n], dx * bm[n]);
                    acc = fmaf(h[n], cm[n], acc);
                    a *= p;
                }
            } else {
#pragma unroll
                for (int n = 0; n < 16; n++) {
                    h[n] = fmaf(__expf(dt * Av[n]), h[n], dx * bm[n]);
                    acc = fmaf(h[n], cm[n], acc);
                }
            }
            yptr[(t0 + u) * D_] = acc;
        }
    }
}

// ---------------------------------------------------------------------------
// Launch
// ---------------------------------------------------------------------------
extern "C" void kernel_launch(void* const* d_in, const int* in_sizes, int n_in,
                              void* d_out, int out_size) {
    const float* x     = (const float*)d_in[0];
    const float* A_log = (const float*)d_in[1];
    const float* W_dbc = (const float*)d_in[2];
    const float* b_dbc = (const float*)d_in[3];
    const float* W_up  = (const float*)d_in[4];
    const float* b_up  = (const float*)d_in[5];
    float* y = (float*)d_out;

    k_gemm_dbc<<<M_ / 32, 256>>>(x, W_dbc, b_dbc);
    k_gemm_delta<<<dim3(M_ / 64, D_ / 64), 256>>>(W_up, b_up);
    k_scanA<<<(NC * CH) / 256, 256>>>(x, A_log);
    k_scanB<<<(CH * N_) / 256, 256>>>(A_log);
    k_scanC<<<(NC * CH) / 256, 256>>>(x, A_log, y);
}

// round 6
// speedup vs baseline: 1.6353x; 1.6353x over previous
#include <cuda_runtime.h>
#include <math.h>

// Problem constants (from reference)
#define B_   2
#define L_   2048
#define D_   1024
#define N_   16
#define R_   64
#define M_   (B_ * L_)        // 4096 rows
#define DBC_ (R_ + 2 * N_)    // 96
#define LC   64               // chunk length
#define NC   (L_ / LC)        // 32 chunks
#define CH   (B_ * D_)        // 2048 channels

typedef unsigned long long u64;

// Packed f32x2 helpers (Blackwell: FFMA2 only via PTX)
__device__ __forceinline__ u64 pack2(float lo, float hi) {
    u64 d; asm("mov.b64 %0, {%1, %2};" : "=l"(d) : "f"(lo), "f"(hi)); return d;
}
__device__ __forceinline__ void unpack2(u64 v, float& lo, float& hi) {
    asm("mov.b64 {%0, %1}, %2;" : "=f"(lo), "=f"(hi) : "l"(v));
}
__device__ __forceinline__ u64 fma2(u64 a, u64 b, u64 c) {
    u64 d; asm("fma.rn.f32x2 %0, %1, %2, %3;" : "=l"(d) : "l"(a), "l"(b), "l"(c)); return d;
}
__device__ __forceinline__ u64 mul2(u64 a, u64 b) {
    u64 d; asm("mul.rn.f32x2 %0, %1, %2;" : "=l"(d) : "l"(a), "l"(b)); return d;
}

// Scratch (no cudaMalloc allowed -> __device__ globals)
__device__ float g_dbc[M_ * DBC_];      // [M, 96]  : delta_low | Bm | Cm
__device__ float g_delta[M_ * D_];      // [M, D]   : softplus(delta_low @ Wup^T + b)
__device__ float g_S[NC * CH];          // per-chunk sum of delta
__device__ float g_hend[NC * CH * N_];  // local chunk-end state (h_in = 0)
__device__ float g_hin[NC * CH * N_];   // corrected chunk-entry state

// ---------------------------------------------------------------------------
// GEMM1: g_dbc[m, j] = sum_k x[m,k] * W_dbc[j,k] + b_dbc[j]
// Tile 32(M) x 96(N) x 32(K), double-buffered smem, LDG->reg staging.
// 256 threads (16x16), per thread 2 rows x 6 cols (3 packed col-pairs).
// ---------------------------------------------------------------------------
#define KT 32
__global__ __launch_bounds__(256) void k_gemm_dbc(const float* __restrict__ X,
                                                  const float* __restrict__ W,
                                                  const float* __restrict__ bias) {
    __shared__ float Xs[2][KT][34];   // [buf][k][m], even stride for LDS.64
    __shared__ float Ws[2][KT][98];   // [buf][k][j]
    const int tid = threadIdx.x;
    const int m0  = blockIdx.x * 32;
    const int ty  = tid >> 4;     // 0..15 -> rows ty*2, ty*2+1
    const int tx  = tid & 15;     // 0..15 -> cols tx*6 .. tx*6+5

    u64 acc[2][3];
#pragma unroll
    for (int i = 0; i < 2; i++)
#pragma unroll
        for (int j = 0; j < 3; j++) acc[i][j] = 0ull;

    // prologue: fill buffer 0 (k0 = 0)
#pragma unroll
    for (int i = 0; i < 4; i++) {          // 32x32 X tile
        int idx = tid + i * 256;
        Xs[0][idx & 31][idx >> 5] = X[(m0 + (idx >> 5)) * 1024 + (idx & 31)];
    }
#pragma unroll
    for (int i = 0; i < 12; i++) {         // 96x32 W tile
        int idx = tid + i * 256;
        Ws[0][idx & 31][idx >> 5] = W[(idx >> 5) * 1024 + (idx & 31)];
    }
    __syncthreads();

    for (int it = 0; it < 1024 / KT; it++) {
        const int cur = it & 1, nxt = cur ^ 1;
        float xr[4], wr[12];
        if (it < 1024 / KT - 1) {          // stage next tile in registers
            const int k0 = (it + 1) * KT;
#pragma unroll
            for (int i = 0; i < 4; i++) {
                int idx = tid + i * 256;
                xr[i] = X[(m0 + (idx >> 5)) * 1024 + k0 + (idx & 31)];
            }
#pragma unroll
            for (int i = 0; i < 12; i++) {
                int idx = tid + i * 256;
                wr[i] = W[(idx >> 5) * 1024 + k0 + (idx & 31)];
            }
        }
#pragma unroll
        for (int kk = 0; kk < KT; kk++) {
            float2 rm = *(const float2*)&Xs[cur][kk][ty * 2];
            float2 n0 = *(const float2*)&Ws[cur][kk][tx * 6];
            float2 n1 = *(const float2*)&Ws[cur][kk][tx * 6 + 2];
            float2 n2 = *(const float2*)&Ws[cur][kk][tx * 6 + 4];
            u64 rm0 = pack2(rm.x, rm.x);
            u64 rm1 = pack2(rm.y, rm.y);
            u64 p0 = *(u64*)&n0, p1 = *(u64*)&n1, p2v = *(u64*)&n2;
            acc[0][0] = fma2(rm0, p0, acc[0][0]);
            acc[0][1] = fma2(rm0, p1, acc[0][1]);
            acc[0][2] = fma2(rm0, p2v, acc[0][2]);
            acc[1][0] = fma2(rm1, p0, acc[1][0]);
            acc[1][1] = fma2(rm1, p1, acc[1][1]);
            acc[1][2] = fma2(rm1, p2v, acc[1][2]);
        }
        if (it < 1024 / KT - 1) {          // commit staged tile
#pragma unroll
            for (int i = 0; i < 4; i++) {
                int idx = tid + i * 256;
                Xs[nxt][idx & 31][idx >> 5] = xr[i];
            }
#pragma unroll
            for (int i = 0; i < 12; i++) {
                int idx = tid + i * 256;
                Ws[nxt][idx & 31][idx >> 5] = wr[i];
            }
        }
        __syncthreads();
    }

#pragma unroll
    for (int i = 0; i < 2; i++)
#pragma unroll
        for (int j = 0; j < 3; j++) {
            float lo, hi;
            unpack2(acc[i][j], lo, hi);
            int col = tx * 6 + 2 * j;
            int row = m0 + ty * 2 + i;
            g_dbc[row * DBC_ + col]     = lo + bias[col];
            g_dbc[row * DBC_ + col + 1] = hi + bias[col + 1];
        }
}

// ---------------------------------------------------------------------------
// GEMM2: g_delta[m, d] = softplus( sum_r g_dbc[m, r] * Wup[d, r] + bup[d] )
// Tile 64(M) x 64(D) x 64(K=R), 256 threads, 4 rows x 4 cols (2 packed pairs).
// ---------------------------------------------------------------------------
__global__ __launch_bounds__(256) void k_gemm_delta(const float* __restrict__ Wup,
                                                    const float* __restrict__ bup) {
    __shared__ float Ls[64][66];   // [r][m], even stride
    __shared__ float Ws2[64][66];  // [r][d]
    const int tid = threadIdx.x;
    const int m0 = blockIdx.x * 64;
    const int d0 = blockIdx.y * 64;

#pragma unroll
    for (int i = 0; i < 16; i++) {
        int idx = tid + i * 256;          // 0..4095
        int a = idx >> 6, rr = idx & 63;
        Ls[rr][a] = g_dbc[(m0 + a) * DBC_ + rr];
        Ws2[rr][a] = Wup[(d0 + a) * R_ + rr];
    }
    __syncthreads();

    const int ty = tid >> 4, tx = tid & 15;
    u64 acc[4][2];
#pragma unroll
    for (int i = 0; i < 4; i++)
#pragma unroll
        for (int j = 0; j < 2; j++) acc[i][j] = 0ull;

#pragma unroll 8
    for (int r = 0; r < 64; r++) {
        float2 a01 = *(const float2*)&Ls[r][ty * 4];
        float2 a23 = *(const float2*)&Ls[r][ty * 4 + 2];
        float2 n01 = *(const float2*)&Ws2[r][tx * 4];
        float2 n23 = *(const float2*)&Ws2[r][tx * 4 + 2];
        u64 p0 = *(u64*)&n01, p1 = *(u64*)&n23;
        u64 b0 = pack2(a01.x, a01.x);
        u64 b1 = pack2(a01.y, a01.y);
        u64 b2 = pack2(a23.x, a23.x);
        u64 b3 = pack2(a23.y, a23.y);
        acc[0][0] = fma2(b0, p0, acc[0][0]); acc[0][1] = fma2(b0, p1, acc[0][1]);
        acc[1][0] = fma2(b1, p0, acc[1][0]); acc[1][1] = fma2(b1, p1, acc[1][1]);
        acc[2][0] = fma2(b2, p0, acc[2][0]); acc[2][1] = fma2(b2, p1, acc[2][1]);
        acc[3][0] = fma2(b3, p0, acc[3][0]); acc[3][1] = fma2(b3, p1, acc[3][1]);
    }
#pragma unroll
    for (int i = 0; i < 4; i++)
#pragma unroll
        for (int j = 0; j < 2; j++) {
            float lo, hi;
            unpack2(acc[i][j], lo, hi);
            int dd = d0 + tx * 4 + 2 * j;
            int row = m0 + ty * 4 + i;
            float v0 = lo + bup[dd];
            float v1 = hi + bup[dd + 1];
            g_delta[row * D_ + dd]     = (v0 > 20.f) ? v0 : log1pf(__expf(v0));
            g_delta[row * D_ + dd + 1] = (v1 > 20.f) ? v1 : log1pf(__expf(v1));
        }
}

// ---------------------------------------------------------------------------
// Helpers for scans
// ---------------------------------------------------------------------------
__device__ __forceinline__ bool load_A(const float* __restrict__ A_log, int d,
                                       float Av[16]) {
    const float4* p = (const float4*)(A_log + d * N_);
    float4 a0 = p[0], a1 = p[1], a2 = p[2], a3 = p[3];
    Av[0] = -__expf(a0.x);  Av[1] = -__expf(a0.y);
    Av[2] = -__expf(a0.z);  Av[3] = -__expf(a0.w);
    Av[4] = -__expf(a1.x);  Av[5] = -__expf(a1.y);
    Av[6] = -__expf(a1.z);  Av[7] = -__expf(a1.w);
    Av[8] = -__expf(a2.x);  Av[9] = -__expf(a2.y);
    Av[10] = -__expf(a2.z); Av[11] = -__expf(a2.w);
    Av[12] = -__expf(a3.x); Av[13] = -__expf(a3.y);
    Av[14] = -__expf(a3.z); Av[15] = -__expf(a3.w);
    bool fast = true;
#pragma unroll
    for (int n = 1; n < 16; n++) {
        float tgt = Av[0] * (float)(n + 1);
        if (fabsf(Av[n] - tgt) > 1e-4f + 1e-5f * fabsf(tgt)) fast = false;
    }
    return fast;
}

__device__ __forceinline__ void load8p(const float* __restrict__ p, u64 v[8]) {
    const ulonglong2* q = (const ulonglong2*)p;   // 16 floats = 8 pairs
    ulonglong2 q0 = q[0], q1 = q[1], q2 = q[2], q3 = q[3];
    v[0] = q0.x; v[1] = q0.y; v[2] = q1.x; v[3] = q1.y;
    v[4] = q2.x; v[5] = q2.y; v[6] = q3.x; v[7] = q3.y;
}

#define UF 8   // timestep staging depth in scan kernels

// ---------------------------------------------------------------------------
// Phase A: per (chunk, b, d) local scan with h_in = 0.
// Fully unrolled double-buffered pipeline (static indices -> registers).
// State held as 8 packed f32x2 pairs; fast path: 1 exp + packed power chain.
// ---------------------------------------------------------------------------
__global__ __launch_bounds__(256) void k_scanA(const float* __restrict__ x,
                                               const float* __restrict__ A_log) {
    const int g = blockIdx.x * 256 + threadIdx.x;   // 65536 threads
    const int d = g & (D_ - 1);
    const int rest = g >> 10;
    const int b = rest & (B_ - 1);
    const int c = rest >> 1;

    float Av[16];
    const bool fast = load_A(A_log, d, Av);
    const float A0 = Av[0];

    u64 h[8];
#pragma unroll
    for (int k = 0; k < 8; k++) h[k] = 0ull;
    float S = 0.f;

    const int trow0 = b * L_ + c * LC;
    const float* dptr = g_delta + trow0 * D_ + d;
    const float* xptr = x + trow0 * D_ + d;

    float dts[2][UF], xts[2][UF];
#pragma unroll
    for (int u = 0; u < UF; u++) {
        dts[0][u] = dptr[u * D_];
        xts[0][u] = xptr[u * D_];
    }

#pragma unroll
    for (int blk = 0; blk < LC / UF; blk++) {
        const int cur = blk & 1, nxt = cur ^ 1;
        if (blk + 1 < LC / UF) {
#pragma unroll
            for (int u = 0; u < UF; u++) {
                dts[nxt][u] = dptr[((blk + 1) * UF + u) * D_];
                xts[nxt][u] = xptr[((blk + 1) * UF + u) * D_];
            }
        }
#pragma unroll
        for (int u = 0; u < UF; u++) {
            const int t = blk * UF + u;
            float dt = dts[cur][u];
            float xt = xts[cur][u];
            S += dt;
            float dx = dt * xt;
            u64 bmp[8];
            load8p(g_dbc + (trow0 + t) * DBC_ + R_, bmp);   // Bm (L2-resident)
            u64 dxp = pack2(dx, dx);
            if (fast) {
                float p = __expf(dt * A0);
                float psq = p * p;
                u64 a = pack2(p, psq);
                u64 P2 = pack2(psq, psq);
#pragma unroll
                for (int k = 0; k < 8; k++) {
                    h[k] = fma2(a, h[k], mul2(dxp, bmp[k]));
                    if (k < 7) a = mul2(a, P2);
                }
            } else {
#pragma unroll
                for (int k = 0; k < 8; k++) {
                    u64 ep = pack2(__expf(dt * Av[2 * k]), __expf(dt * Av[2 * k + 1]));
                    h[k] = fma2(ep, h[k], mul2(dxp, bmp[k]));
                }
            }
        }
    }

    const int ch = b * D_ + d;
    ulonglong2* hp = (ulonglong2*)(g_hend + (c * CH + ch) * N_);
    hp[0] = make_ulonglong2(h[0], h[1]);
    hp[1] = make_ulonglong2(h[2], h[3]);
    hp[2] = make_ulonglong2(h[4], h[5]);
    hp[3] = make_ulonglong2(h[6], h[7]);
    g_S[c * CH + ch] = S;
}

// ---------------------------------------------------------------------------
// Phase B: sequential combine across 32 chunks per (channel, n).
// Fully unrolled: all 64 loads in flight, 32 parallel exps, serial fma chain.
// ---------------------------------------------------------------------------
__global__ __launch_bounds__(256) void k_scanB(const float* __restrict__ A_log) {
    const int g = blockIdx.x * 256 + threadIdx.x;   // 32768 threads
    const int n = g & (N_ - 1);
    const int ch = g >> 4;
    const int d = ch & (D_ - 1);
    const float An = -__expf(A_log[d * N_ + n]);

    float e[NC], hb[NC];
#pragma unroll
    for (int c = 0; c < NC; c++) e[c] = g_S[c * CH + ch];
#pragma unroll
    for (int c = 0; c < NC; c++) hb[c] = g_hend[(c * CH + ch) * N_ + n];
#pragma unroll
    for (int c = 0; c < NC; c++) e[c] = __expf(An * e[c]);

    float h = 0.f;
#pragma unroll
    for (int c = 0; c < NC; c++) {
        g_hin[(c * CH + ch) * N_ + n] = h;
        h = fmaf(e[c], h, hb[c]);
    }
}

// ---------------------------------------------------------------------------
// Phase C: replay each chunk from corrected h_in, emit y_t = sum_n h_n * C_n.
// Same fully-unrolled double-buffered pipeline + packed math as phase A.
// ---------------------------------------------------------------------------
__global__ __launch_bounds__(256) void k_scanC(const float* __restrict__ x,
                                               const float* __restrict__ A_log,
                                               float* __restrict__ y) {
    const int g = blockIdx.x * 256 + threadIdx.x;   // 65536 threads
    const int d = g & (D_ - 1);
    const int rest = g >> 10;
    const int b = rest & (B_ - 1);
    const int c = rest >> 1;

    float Av[16];
    const bool fast = load_A(A_log, d, Av);
    const float A0 = Av[0];

    const int ch = b * D_ + d;
    u64 h[8];
    load8p(g_hin + (c * CH + ch) * N_, h);

    const int trow0 = b * L_ + c * LC;
    const float* dptr = g_delta + trow0 * D_ + d;
    const float* xptr = x + trow0 * D_ + d;
    float* yptr = y + trow0 * D_ + d;

    float dts[2][UF], xts[2][UF];
#pragma unroll
    for (int u = 0; u < UF; u++) {
        dts[0][u] = dptr[u * D_];
        xts[0][u] = xptr[u * D_];
    }

#pragma unroll
    for (int blk = 0; blk < LC / UF; blk++) {
        const int cur = blk & 1, nxt = cur ^ 1;
        if (blk + 1 < LC / UF) {
#pragma unroll
            for (int u = 0; u < UF; u++) {
                dts[nxt][u] = dptr[((blk + 1) * UF + u) * D_];
                xts[nxt][u] = xptr[((blk + 1) * UF + u) * D_];
            }
        }
#pragma unroll
        for (int u = 0; u < UF; u++) {
            const int t = blk * UF + u;
            float dt = dts[cur][u];
            float xt = xts[cur][u];
            float dx = dt * xt;
            const float* row = g_dbc + (trow0 + t) * DBC_;
            u64 bmp[8], cmp[8];
            load8p(row + R_, bmp);         // Bm
            load8p(row + R_ + N_, cmp);    // Cm
            u64 dxp = pack2(dx, dx);
            u64 accp = 0ull;
            if (fast) {
                float p = __expf(dt * A0);
                float psq = p * p;
                u64 a = pack2(p, psq);
                u64 P2 = pack2(psq, psq);
#pragma unroll
                for (int k = 0; k < 8; k++) {
                    h[k] = fma2(a, h[k], mul2(dxp, bmp[k]));
                    accp = fma2(h[k], cmp[k], accp);
                    if (k < 7) a = mul2(a, P2);
                }
            } else {
#pragma unroll
                for (int k = 0; k < 8; k++) {
                    u64 ep = pack2(__expf(dt * Av[2 * k]), __expf(dt * Av[2 * k + 1]));
                    h[k] = fma2(ep, h[k], mul2(dxp, bmp[k]));
                    accp = fma2(h[k], cmp[k], accp);
                }
            }
            float alo, ahi;
            unpack2(accp, alo, ahi);
            yptr[t * D_] = alo + ahi;
        }
    }
}

// ---------------------------------------------------------------------------
// Launch
// ---------------------------------------------------------------------------
extern "C" void kernel_launch(void* const* d_in, const int* in_sizes, int n_in,
                              void* d_out, int out_size) {
    const float* x     = (const float*)d_in[0];
    const float* A_log = (const float*)d_in[1];
    const float* W_dbc = (const float*)d_in[2];
    const float* b_dbc = (const float*)d_in[3];
    const float* W_up  = (const float*)d_in[4];
    const float* b_up  = (const float*)d_in[5];
    float* y = (float*)d_out;

    k_gemm_dbc<<<M_ / 32, 256>>>(x, W_dbc, b_dbc);
    k_gemm_delta<<<dim3(M_ / 64, D_ / 64), 256>>>(W_up, b_up);
    k_scanA<<<(NC * CH) / 256, 256>>>(x, A_log);
    k_scanB<<<(CH * N_) / 256, 256>>>(A_log);
    k_scanC<<<(NC * CH) / 256, 256>>>(x, A_log, y);
}